// round 8
// baseline (speedup 1.0000x reference)
#include <cuda_runtime.h>
#include <cuda_bf16.h>
#include <cstdint>

#define EPSF 1e-5f
#define QBF  127.0f

static constexpr int MTOK  = 4 * 4096;
static constexpr int DIN   = 1024;
static constexpr int INNER = 4096;

// ---------------- device scratch ----------------
__device__ float g_wfac[2];
__device__ float g_part[2][256];
__device__ __align__(16) __nv_bfloat16 g_w1q[(size_t)INNER * DIN];
__device__ __align__(16) __nv_bfloat16 g_w2q[(size_t)DIN * INNER];
__device__ __align__(16) __nv_bfloat16 g_xq [(size_t)MTOK * DIN];
__device__ float g_sx[MTOK];
__device__ __align__(16) float g_h [(size_t)MTOK * INNER];
__device__ __align__(16) __nv_bfloat16 g_hq[(size_t)MTOK * INNER];
__device__ float g_sh[MTOK];
// per-(row, 64-col tile) partial stats of h, written by gemm1 epilogue
__device__ __align__(16) float g_hss[(size_t)MTOK * 64];
__device__ __align__(16) float g_ham[(size_t)MTOK * 64];

// ---------------- helpers ----------------
__device__ __forceinline__ uint32_t smem_u32(const void* p) {
    uint32_t a;
    asm("{ .reg .u64 t; cvta.to.shared.u64 t, %1; cvt.u32.u64 %0, t; }" : "=r"(a) : "l"(p));
    return a;
}
__device__ __forceinline__ void cp_async16(uint32_t dst, const void* src) {
    asm volatile("cp.async.cg.shared.global [%0], [%1], 16;" :: "r"(dst), "l"(src) : "memory");
}
#define CP_COMMIT()  asm volatile("cp.async.commit_group;" ::: "memory")
#define CP_WAIT(N)   asm volatile("cp.async.wait_group %0;" :: "n"(N) : "memory")

__device__ __forceinline__ void ldmx4(uint32_t& r0, uint32_t& r1, uint32_t& r2, uint32_t& r3,
                                      uint32_t addr) {
    asm volatile("ldmatrix.sync.aligned.m8n8.x4.shared.b16 {%0,%1,%2,%3}, [%4];"
                 : "=r"(r0), "=r"(r1), "=r"(r2), "=r"(r3) : "r"(addr));
}
__device__ __forceinline__ void mma_bf16(float* c, const uint32_t* a, const uint32_t* b) {
    asm volatile("mma.sync.aligned.m16n8k16.row.col.f32.bf16.bf16.f32 "
                 "{%0,%1,%2,%3}, {%4,%5,%6,%7}, {%8,%9}, {%0,%1,%2,%3};"
                 : "+f"(c[0]), "+f"(c[1]), "+f"(c[2]), "+f"(c[3])
                 : "r"(a[0]), "r"(a[1]), "r"(a[2]), "r"(a[3]), "r"(b[0]), "r"(b[1]));
}

// ---------------- weight absmean partials (both weights) -----------------
__global__ void wabs_part(const float* __restrict__ w1, const float* __restrict__ w2,
                          int n) {
    int slot = blockIdx.y;
    const float4* w4 = (const float4*)(slot ? w2 : w1);
    int nv = n >> 2;
    float s = 0.f;
    for (int i = blockIdx.x * blockDim.x + threadIdx.x; i < nv; i += gridDim.x * blockDim.x) {
        float4 v = w4[i];
        s += fabsf(v.x) + fabsf(v.y) + fabsf(v.z) + fabsf(v.w);
    }
    __shared__ float sh[256];
    sh[threadIdx.x] = s;
    __syncthreads();
    for (int o = 128; o > 0; o >>= 1) {
        if (threadIdx.x < o) sh[threadIdx.x] += sh[threadIdx.x + o];
        __syncthreads();
    }
    if (threadIdx.x == 0) g_part[slot][blockIdx.x] = sh[0];
}

// ---------------- ternary weight quant (inlines the final reduce) --------
__global__ void wquant(const float* __restrict__ w1, const float* __restrict__ w2, int n) {
    int slot = blockIdx.y;
    __shared__ float sh[256];
    sh[threadIdx.x] = g_part[slot][threadIdx.x];
    __syncthreads();
    for (int o = 128; o > 0; o >>= 1) {
        if (threadIdx.x < o) sh[threadIdx.x] += sh[threadIdx.x + o];
        __syncthreads();
    }
    float wf = fmaxf(sh[0] / (float)n, EPSF);
    if (blockIdx.x == 0 && threadIdx.x == 0) g_wfac[slot] = wf;

    const float* w = slot ? w2 : w1;
    __nv_bfloat16* q = slot ? g_w2q : g_w1q;
    int i = blockIdx.x * blockDim.x + threadIdx.x;
    int nv = n >> 2;
    if (i >= nv) return;
    float sc = 1.f / wf;
    float4 v = ((const float4*)w)[i];
    int t0 = (int)rintf(v.x * sc); t0 = t0 < -1 ? -1 : (t0 > 1 ? 1 : t0);
    int t1 = (int)rintf(v.y * sc); t1 = t1 < -1 ? -1 : (t1 > 1 ? 1 : t1);
    int t2 = (int)rintf(v.z * sc); t2 = t2 < -1 ? -1 : (t2 > 1 ? 1 : t2);
    int t3 = (int)rintf(v.w * sc); t3 = t3 < -1 ? -1 : (t3 > 1 ? 1 : t3);
    __nv_bfloat162* q2 = (__nv_bfloat162*)(q + (size_t)i * 4);
    q2[0] = __nv_bfloat162(__float2bfloat16_rn((float)t0), __float2bfloat16_rn((float)t1));
    q2[1] = __nv_bfloat162(__float2bfloat16_rn((float)t2), __float2bfloat16_rn((float)t3));
}

// ---------------- rmsnorm + absmax int8 quant, warp-per-row --------------
__global__ __launch_bounds__(256)
void act_quant(const float* __restrict__ xin, int slot) {
    const int lane = threadIdx.x & 31;
    const int wrow = blockIdx.x * 8 + (threadIdx.x >> 5);

    if (slot == 0) {
        const float4* xr = (const float4*)(xin + (size_t)wrow * DIN);
        float4 v[8];
        float ss = 0.f, am = 0.f;
#pragma unroll
        for (int i = 0; i < 8; i++) {
            float4 f = xr[lane + 32 * i];
            v[i] = f;
            ss += f.x * f.x + f.y * f.y + f.z * f.z + f.w * f.w;
            am = fmaxf(am, fmaxf(fmaxf(fabsf(f.x), fabsf(f.y)), fmaxf(fabsf(f.z), fabsf(f.w))));
        }
#pragma unroll
        for (int o = 16; o > 0; o >>= 1) {
            ss += __shfl_xor_sync(0xffffffffu, ss, o);
            am = fmaxf(am, __shfl_xor_sync(0xffffffffu, am, o));
        }
        float rn = rsqrtf(ss / (float)DIN + EPSF);
        float amn = fmaxf(am * rn, EPSF);
        float sc = QBF / amn;
        if (lane == 0) g_sx[wrow] = amn / QBF;

        uint2* qr = (uint2*)(g_xq + (size_t)wrow * DIN);
#pragma unroll
        for (int i = 0; i < 8; i++) {
            float4 f = v[i];
            int t0 = (int)rintf((f.x * rn) * sc); t0 = t0 < -128 ? -128 : (t0 > 127 ? 127 : t0);
            int t1 = (int)rintf((f.y * rn) * sc); t1 = t1 < -128 ? -128 : (t1 > 127 ? 127 : t1);
            int t2 = (int)rintf((f.z * rn) * sc); t2 = t2 < -128 ? -128 : (t2 > 127 ? 127 : t2);
            int t3 = (int)rintf((f.w * rn) * sc); t3 = t3 < -128 ? -128 : (t3 > 127 ? 127 : t3);
            __nv_bfloat162 p0(__float2bfloat16_rn((float)t0), __float2bfloat16_rn((float)t1));
            __nv_bfloat162 p1(__float2bfloat16_rn((float)t2), __float2bfloat16_rn((float)t3));
            uint2 u;
            u.x = *(uint32_t*)&p0;
            u.y = *(uint32_t*)&p1;
            qr[lane + 32 * i] = u;
        }
    } else {
        // single pass: stats come from gemm1 epilogue partials
        float2 s2 = ((const float2*)(g_hss + (size_t)wrow * 64))[lane];
        float2 a2 = ((const float2*)(g_ham + (size_t)wrow * 64))[lane];
        float ss = s2.x + s2.y;
        float am = fmaxf(a2.x, a2.y);
#pragma unroll
        for (int o = 16; o > 0; o >>= 1) {
            ss += __shfl_xor_sync(0xffffffffu, ss, o);
            am = fmaxf(am, __shfl_xor_sync(0xffffffffu, am, o));
        }
        float rn = rsqrtf(ss / (float)INNER + EPSF);
        float amn = fmaxf(am * rn, EPSF);
        float sc = QBF / amn;
        if (lane == 0) g_sh[wrow] = amn / QBF;

        const float4* xr = (const float4*)(g_h + (size_t)wrow * INNER);
        uint2* qr = (uint2*)(g_hq + (size_t)wrow * INNER);
#pragma unroll 4
        for (int i = 0; i < 32; i++) {
            float4 f = xr[lane + 32 * i];
            int t0 = (int)rintf((f.x * rn) * sc); t0 = t0 < -128 ? -128 : (t0 > 127 ? 127 : t0);
            int t1 = (int)rintf((f.y * rn) * sc); t1 = t1 < -128 ? -128 : (t1 > 127 ? 127 : t1);
            int t2 = (int)rintf((f.z * rn) * sc); t2 = t2 < -128 ? -128 : (t2 > 127 ? 127 : t2);
            int t3 = (int)rintf((f.w * rn) * sc); t3 = t3 < -128 ? -128 : (t3 > 127 ? 127 : t3);
            __nv_bfloat162 p0(__float2bfloat16_rn((float)t0), __float2bfloat16_rn((float)t1));
            __nv_bfloat162 p1(__float2bfloat16_rn((float)t2), __float2bfloat16_rn((float)t3));
            uint2 u;
            u.x = *(uint32_t*)&p0;
            u.y = *(uint32_t*)&p1;
            qr[lane + 32 * i] = u;
        }
    }
}

// ---------------- bf16 HMMA GEMM: CTA 128x256, warp 64x64, 4 stages -------
static constexpr int BM = 128, BN = 256, BKE = 64;            // 128 B of K per stage
static constexpr int A_BYTES = BM * BKE * 2;                  // 16 KB
static constexpr int STAGE_BYTES = (BM + BN) * BKE * 2;       // 48 KB
static constexpr int STAGES = 4;
static constexpr int SMEM_BYTES = STAGES * STAGE_BYTES;       // 192 KB

__global__ __launch_bounds__(256, 1)
void gemm_bf16(const float* __restrict__ bias, float* __restrict__ dout, int layer) {
    const __nv_bfloat16 *A, *B;
    const float* inva;
    float* out;
    int N, K;
    if (layer == 0) { A = g_xq; B = g_w1q; inva = g_sx; out = g_h;  N = INNER; K = DIN;  }
    else            { A = g_hq; B = g_w2q; inva = g_sh; out = dout; N = DIN;   K = INNER; }

    extern __shared__ char smem[];
    const uint32_t sb = smem_u32(smem);

    const int tid = threadIdx.x;
    const int wid = tid >> 5, lid = tid & 31;
    const int wm = wid >> 2, wn = wid & 3;        // 2 x 4 warps, each 64m x 64n
    const int m0 = blockIdx.y * BM;
    const int n0 = blockIdx.x * BN;

    float acc[4][8][4];
#pragma unroll
    for (int i = 0; i < 4; i++)
#pragma unroll
        for (int j = 0; j < 8; j++)
#pragma unroll
            for (int q = 0; q < 4; q++) acc[i][j][q] = 0.f;

    const int nk = K / BKE;

    // ----- precomputed cp.async addressing -----
    const int lrow = tid >> 3;                    // 0..31, +32 per t
    const uint32_t swz0 = (uint32_t)lrow * 128u + (((tid & 7) * 16) ^ ((lrow & 7) << 4));
    const __nv_bfloat16* gA = A + (size_t)(m0 + lrow) * K + (tid & 7) * 8;
    const __nv_bfloat16* gB = B + (size_t)(n0 + lrow) * K + (tid & 7) * 8;

    auto load_stage = [&](int c) {
        uint32_t base = sb + (uint32_t)(c & (STAGES - 1)) * STAGE_BYTES + swz0;
        const __nv_bfloat16* a = gA + c * BKE;
        const __nv_bfloat16* b = gB + c * BKE;
#pragma unroll
        for (int t = 0; t < 4; t++)                     // A: 128 rows
            cp_async16(base + t * 4096u, a + (size_t)t * 32 * K);
#pragma unroll
        for (int t = 0; t < 8; t++)                     // B: 256 rows
            cp_async16(base + (uint32_t)A_BYTES + t * 4096u, b + (size_t)t * 32 * K);
        CP_COMMIT();
    };

    // ----- ldmatrix lane addressing -----
    const int ltile = lid >> 3, lr = lid & 7;
    uint32_t a_off[4], a_xor[4];
    const uint32_t a_kadd = (ltile >> 1) * 16;
#pragma unroll
    for (int i = 0; i < 4; i++) {
        uint32_t row = wm * 64 + i * 16 + (ltile & 1) * 8 + lr;
        a_off[i] = row * 128u;
        a_xor[i] = (row & 7u) << 4;
    }
    uint32_t b_off[4], b_xor[4];
    const uint32_t b_kadd = (ltile & 1) * 16;
#pragma unroll
    for (int jb = 0; jb < 4; jb++) {
        uint32_t row = wn * 64 + jb * 16 + (ltile >> 1) * 8 + lr;
        b_off[jb] = row * 128u;
        b_xor[jb] = (row & 7u) << 4;
    }

    load_stage(0);
    load_stage(1);
    load_stage(2);

    for (int c = 0; c < nk; c++) {
        if (c + 3 < nk) { CP_WAIT(2); } else if (c + 2 < nk) { CP_WAIT(1); } else { CP_WAIT(0); }
        __syncthreads();

        // issue next stage before compute; its buffer (c+3)%4 == (c-1)%4 is free
        if (c + 3 < nk) load_stage(c + 3);

        uint32_t baseA = sb + (uint32_t)(c & (STAGES - 1)) * STAGE_BYTES;
        uint32_t baseB = baseA + (uint32_t)A_BYTES;

#pragma unroll
        for (int ks = 0; ks < 4; ks++) {
            uint32_t kbA = ks * 32 + a_kadd;
            uint32_t kbB = ks * 32 + b_kadd;
            uint32_t afr[4][4];
#pragma unroll
            for (int i = 0; i < 4; i++)
                ldmx4(afr[i][0], afr[i][1], afr[i][2], afr[i][3],
                      baseA + a_off[i] + (kbA ^ a_xor[i]));
            uint32_t bfr[8][2];
#pragma unroll
            for (int jb = 0; jb < 4; jb++) {
                uint32_t r0, r1, r2, r3;
                ldmx4(r0, r1, r2, r3, baseB + b_off[jb] + (kbB ^ b_xor[jb]));
                bfr[jb * 2 + 0][0] = r0; bfr[jb * 2 + 0][1] = r1;
                bfr[jb * 2 + 1][0] = r2; bfr[jb * 2 + 1][1] = r3;
            }
#pragma unroll
            for (int i = 0; i < 4; i++)
#pragma unroll
                for (int j = 0; j < 8; j++)
                    mma_bf16(acc[i][j], afr[i], bfr[j]);
        }
    }

    // ----- epilogue -----
    const float fw = g_wfac[layer];
    const int g = lid >> 2, tig = lid & 3;
    const int tile64 = blockIdx.x * 4 + wn;       // 64-col tile index (layer 0 stats)
#pragma unroll
    for (int i = 0; i < 4; i++) {
        int r0 = m0 + wm * 64 + i * 16 + g;
        float fa0 = inva[r0] * fw;
        float fa1 = inva[r0 + 8] * fw;
        float ssa = 0.f, ama = 0.f, ssb = 0.f, amb = 0.f;
#pragma unroll
        for (int j = 0; j < 8; j++) {
            int n = n0 + wn * 64 + j * 8 + tig * 2;
            float bx = bias[n], by = bias[n + 1];
            float v0 = acc[i][j][0] * fa0 + bx;
            float v1 = acc[i][j][1] * fa0 + by;
            float v2 = acc[i][j][2] * fa1 + bx;
            float v3 = acc[i][j][3] * fa1 + by;
            if (layer == 0) {
                v0 = 0.5f * v0 * (1.f + erff(v0 * 0.70710678118654752f));
                v1 = 0.5f * v1 * (1.f + erff(v1 * 0.70710678118654752f));
                v2 = 0.5f * v2 * (1.f + erff(v2 * 0.70710678118654752f));
                v3 = 0.5f * v3 * (1.f + erff(v3 * 0.70710678118654752f));
                ssa += v0 * v0 + v1 * v1;
                ssb += v2 * v2 + v3 * v3;
                ama = fmaxf(ama, fmaxf(fabsf(v0), fabsf(v1)));
                amb = fmaxf(amb, fmaxf(fabsf(v2), fabsf(v3)));
            }
            *(float2*)(out + (size_t)r0 * N + n)       = make_float2(v0, v1);
            *(float2*)(out + (size_t)(r0 + 8) * N + n) = make_float2(v2, v3);
        }
        if (layer == 0) {
#pragma unroll
            for (int o = 1; o < 4; o <<= 1) {
                ssa += __shfl_xor_sync(0xffffffffu, ssa, o);
                ssb += __shfl_xor_sync(0xffffffffu, ssb, o);
                ama = fmaxf(ama, __shfl_xor_sync(0xffffffffu, ama, o));
                amb = fmaxf(amb, __shfl_xor_sync(0xffffffffu, amb, o));
            }
            if (tig == 0) {
                g_hss[(size_t)r0 * 64 + tile64]       = ssa;
                g_ham[(size_t)r0 * 64 + tile64]       = ama;
                g_hss[(size_t)(r0 + 8) * 64 + tile64] = ssb;
                g_ham[(size_t)(r0 + 8) * 64 + tile64] = amb;
            }
        }
    }
}

// -------------------------------------------------------------------------
extern "C" void kernel_launch(void* const* d_in, const int* in_sizes, int n_in,
                              void* d_out, int out_size) {
    const float* x  = (const float*)d_in[0];
    const float* w1 = (const float*)d_in[1];
    const float* b1 = (const float*)d_in[2];
    const float* w2 = (const float*)d_in[3];
    const float* b2 = (const float*)d_in[4];
    float* out = (float*)d_out;

    const int n = INNER * DIN;

    cudaFuncSetAttribute(gemm_bf16, cudaFuncAttributeMaxDynamicSharedMemorySize, SMEM_BYTES);

    wabs_part<<<dim3(256, 2), 256>>>(w1, w2, n);                 // 0
    wquant<<<dim3(n / 4 / 256, 2), 256>>>(w1, w2, n);            // 1
    act_quant<<<MTOK / 8, 256>>>(x, 0);                          // 2
    gemm_bf16<<<dim3(INNER / BN, MTOK / BM), 256, SMEM_BYTES>>>(b1, nullptr, 0);  // 3
    act_quant<<<MTOK / 8, 256>>>(nullptr, 1);                    // 4
    gemm_bf16<<<dim3(DIN / BN, MTOK / BM), 256, SMEM_BYTES>>>(b2, out, 1);        // 5
}

// round 9
// speedup vs baseline: 1.1176x; 1.1176x over previous
#include <cuda_runtime.h>
#include <cuda_bf16.h>
#include <cstdint>

#define EPSF 1e-5f
#define QBF  127.0f

static constexpr int MTOK  = 4 * 4096;
static constexpr int DIN   = 1024;
static constexpr int INNER = 4096;

// ---------------- device scratch ----------------
__device__ float g_wfac[2];
__device__ float g_part[2][256];
__device__ __align__(16) __nv_bfloat16 g_w1q[(size_t)INNER * DIN];
__device__ __align__(16) __nv_bfloat16 g_w2q[(size_t)DIN * INNER];
__device__ __align__(16) __nv_bfloat16 g_xq [(size_t)MTOK * DIN];
__device__ float g_sx[MTOK];
__device__ __align__(16) float g_h [(size_t)MTOK * INNER];
__device__ __align__(16) __nv_bfloat16 g_hq[(size_t)MTOK * INNER];
__device__ float g_sh[MTOK];
__device__ __align__(16) float g_hss[(size_t)MTOK * 64];
__device__ __align__(16) float g_ham[(size_t)MTOK * 64];

// ---------------- helpers ----------------
__device__ __forceinline__ uint32_t smem_u32(const void* p) {
    uint32_t a;
    asm("{ .reg .u64 t; cvta.to.shared.u64 t, %1; cvt.u32.u64 %0, t; }" : "=r"(a) : "l"(p));
    return a;
}
__device__ __forceinline__ void cp_async16(uint32_t dst, const void* src) {
    asm volatile("cp.async.cg.shared.global [%0], [%1], 16;" :: "r"(dst), "l"(src) : "memory");
}
#define CP_COMMIT()  asm volatile("cp.async.commit_group;" ::: "memory")
#define CP_WAIT(N)   asm volatile("cp.async.wait_group %0;" :: "n"(N) : "memory")

__device__ __forceinline__ void ldmx4(uint32_t& r0, uint32_t& r1, uint32_t& r2, uint32_t& r3,
                                      uint32_t addr) {
    asm volatile("ldmatrix.sync.aligned.m8n8.x4.shared.b16 {%0,%1,%2,%3}, [%4];"
                 : "=r"(r0), "=r"(r1), "=r"(r2), "=r"(r3) : "r"(addr));
}
__device__ __forceinline__ void mma_bf16(float* c, const uint32_t* a, const uint32_t* b) {
    asm volatile("mma.sync.aligned.m16n8k16.row.col.f32.bf16.bf16.f32 "
                 "{%0,%1,%2,%3}, {%4,%5,%6,%7}, {%8,%9}, {%0,%1,%2,%3};"
                 : "+f"(c[0]), "+f"(c[1]), "+f"(c[2]), "+f"(c[3])
                 : "r"(a[0]), "r"(a[1]), "r"(a[2]), "r"(a[3]), "r"(b[0]), "r"(b[1]));
}

// ---------------- weight absmean partials (both weights) -----------------
__global__ void wabs_part(const float* __restrict__ w1, const float* __restrict__ w2,
                          int n) {
    int slot = blockIdx.y;
    const float4* w4 = (const float4*)(slot ? w2 : w1);
    int nv = n >> 2;
    float s = 0.f;
    for (int i = blockIdx.x * blockDim.x + threadIdx.x; i < nv; i += gridDim.x * blockDim.x) {
        float4 v = w4[i];
        s += fabsf(v.x) + fabsf(v.y) + fabsf(v.z) + fabsf(v.w);
    }
    __shared__ float sh[256];
    sh[threadIdx.x] = s;
    __syncthreads();
    for (int o = 128; o > 0; o >>= 1) {
        if (threadIdx.x < o) sh[threadIdx.x] += sh[threadIdx.x + o];
        __syncthreads();
    }
    if (threadIdx.x == 0) g_part[slot][blockIdx.x] = sh[0];
}

// ---------------- ternary weight quant (inlines the final reduce) --------
__global__ void wquant(const float* __restrict__ w1, const float* __restrict__ w2, int n) {
    int slot = blockIdx.y;
    __shared__ float sh[256];
    sh[threadIdx.x] = g_part[slot][threadIdx.x];
    __syncthreads();
    for (int o = 128; o > 0; o >>= 1) {
        if (threadIdx.x < o) sh[threadIdx.x] += sh[threadIdx.x + o];
        __syncthreads();
    }
    float wf = fmaxf(sh[0] / (float)n, EPSF);
    if (blockIdx.x == 0 && threadIdx.x == 0) g_wfac[slot] = wf;

    const float* w = slot ? w2 : w1;
    __nv_bfloat16* q = slot ? g_w2q : g_w1q;
    int i = blockIdx.x * blockDim.x + threadIdx.x;
    int nv = n >> 2;
    if (i >= nv) return;
    float sc = 1.f / wf;
    float4 v = ((const float4*)w)[i];
    int t0 = (int)rintf(v.x * sc); t0 = t0 < -1 ? -1 : (t0 > 1 ? 1 : t0);
    int t1 = (int)rintf(v.y * sc); t1 = t1 < -1 ? -1 : (t1 > 1 ? 1 : t1);
    int t2 = (int)rintf(v.z * sc); t2 = t2 < -1 ? -1 : (t2 > 1 ? 1 : t2);
    int t3 = (int)rintf(v.w * sc); t3 = t3 < -1 ? -1 : (t3 > 1 ? 1 : t3);
    __nv_bfloat162* q2 = (__nv_bfloat162*)(q + (size_t)i * 4);
    q2[0] = __nv_bfloat162(__float2bfloat16_rn((float)t0), __float2bfloat16_rn((float)t1));
    q2[1] = __nv_bfloat162(__float2bfloat16_rn((float)t2), __float2bfloat16_rn((float)t3));
}

// ---------------- rmsnorm + absmax int8 quant, warp-per-row --------------
__global__ __launch_bounds__(256)
void act_quant(const float* __restrict__ xin, int slot) {
    const int lane = threadIdx.x & 31;
    const int wrow = blockIdx.x * 8 + (threadIdx.x >> 5);

    if (slot == 0) {
        const float4* xr = (const float4*)(xin + (size_t)wrow * DIN);
        float4 v[8];
        float ss = 0.f, am = 0.f;
#pragma unroll
        for (int i = 0; i < 8; i++) {
            float4 f = xr[lane + 32 * i];
            v[i] = f;
            ss += f.x * f.x + f.y * f.y + f.z * f.z + f.w * f.w;
            am = fmaxf(am, fmaxf(fmaxf(fabsf(f.x), fabsf(f.y)), fmaxf(fabsf(f.z), fabsf(f.w))));
        }
#pragma unroll
        for (int o = 16; o > 0; o >>= 1) {
            ss += __shfl_xor_sync(0xffffffffu, ss, o);
            am = fmaxf(am, __shfl_xor_sync(0xffffffffu, am, o));
        }
        float rn = rsqrtf(ss / (float)DIN + EPSF);
        float amn = fmaxf(am * rn, EPSF);
        float sc = QBF / amn;
        if (lane == 0) g_sx[wrow] = amn / QBF;

        uint2* qr = (uint2*)(g_xq + (size_t)wrow * DIN);
#pragma unroll
        for (int i = 0; i < 8; i++) {
            float4 f = v[i];
            int t0 = (int)rintf((f.x * rn) * sc); t0 = t0 < -128 ? -128 : (t0 > 127 ? 127 : t0);
            int t1 = (int)rintf((f.y * rn) * sc); t1 = t1 < -128 ? -128 : (t1 > 127 ? 127 : t1);
            int t2 = (int)rintf((f.z * rn) * sc); t2 = t2 < -128 ? -128 : (t2 > 127 ? 127 : t2);
            int t3 = (int)rintf((f.w * rn) * sc); t3 = t3 < -128 ? -128 : (t3 > 127 ? 127 : t3);
            __nv_bfloat162 p0(__float2bfloat16_rn((float)t0), __float2bfloat16_rn((float)t1));
            __nv_bfloat162 p1(__float2bfloat16_rn((float)t2), __float2bfloat16_rn((float)t3));
            uint2 u;
            u.x = *(uint32_t*)&p0;
            u.y = *(uint32_t*)&p1;
            qr[lane + 32 * i] = u;
        }
    } else {
        float2 s2 = ((const float2*)(g_hss + (size_t)wrow * 64))[lane];
        float2 a2 = ((const float2*)(g_ham + (size_t)wrow * 64))[lane];
        float ss = s2.x + s2.y;
        float am = fmaxf(a2.x, a2.y);
#pragma unroll
        for (int o = 16; o > 0; o >>= 1) {
            ss += __shfl_xor_sync(0xffffffffu, ss, o);
            am = fmaxf(am, __shfl_xor_sync(0xffffffffu, am, o));
        }
        float rn = rsqrtf(ss / (float)INNER + EPSF);
        float amn = fmaxf(am * rn, EPSF);
        float sc = QBF / amn;
        if (lane == 0) g_sh[wrow] = amn / QBF;

        const float4* xr = (const float4*)(g_h + (size_t)wrow * INNER);
        uint2* qr = (uint2*)(g_hq + (size_t)wrow * INNER);
#pragma unroll 4
        for (int i = 0; i < 32; i++) {
            float4 f = xr[lane + 32 * i];
            int t0 = (int)rintf((f.x * rn) * sc); t0 = t0 < -128 ? -128 : (t0 > 127 ? 127 : t0);
            int t1 = (int)rintf((f.y * rn) * sc); t1 = t1 < -128 ? -128 : (t1 > 127 ? 127 : t1);
            int t2 = (int)rintf((f.z * rn) * sc); t2 = t2 < -128 ? -128 : (t2 > 127 ? 127 : t2);
            int t3 = (int)rintf((f.w * rn) * sc); t3 = t3 < -128 ? -128 : (t3 > 127 ? 127 : t3);
            __nv_bfloat162 p0(__float2bfloat16_rn((float)t0), __float2bfloat16_rn((float)t1));
            __nv_bfloat162 p1(__float2bfloat16_rn((float)t2), __float2bfloat16_rn((float)t3));
            uint2 u;
            u.x = *(uint32_t*)&p0;
            u.y = *(uint32_t*)&p1;
            qr[lane + 32 * i] = u;
        }
    }
}

// ---------------- persistent bf16 HMMA GEMM: CTA 128x128, warp 32x64 ------
static constexpr int BM = 128, BN = 128, BKE = 64;            // 128 B of K per stage
static constexpr int A_BYTES = BM * BKE * 2;                  // 16 KB
static constexpr int STAGE_BYTES = (BM + BN) * BKE * 2;       // 32 KB
static constexpr int NBUF = 3;
static constexpr int SMEM_BYTES = NBUF * STAGE_BYTES;         // 96 KB

template<int LAYER>
__global__ __launch_bounds__(256, 2)
void gemm_bf16(const float* __restrict__ bias, float* __restrict__ dout) {
    constexpr int K   = LAYER ? INNER : DIN;
    constexpr int N   = LAYER ? DIN : INNER;
    constexpr int NK  = K / BKE;                 // stages per tile (16 or 64)
    constexpr int NBX = N / BN;                  // tiles across N (32 or 8)
    constexpr int NTILES = (MTOK / BM) * NBX;    // 4096 or 1024

    const __nv_bfloat16* A = LAYER ? g_hq : g_xq;
    const __nv_bfloat16* B = LAYER ? g_w2q : g_w1q;
    const float* inva      = LAYER ? g_sh : g_sx;
    float* out             = LAYER ? dout : g_h;

    extern __shared__ char smem[];
    const uint32_t sb = smem_u32(smem);

    const int tid = threadIdx.x;
    const int wid = tid >> 5, lid = tid & 31;
    const int wm = wid >> 1, wn = wid & 1;       // 4 x 2 warps, each 32m x 64n
    const int cta = blockIdx.x;
    const int grid = gridDim.x;

    // ----- cp.async per-thread constants -----
    const int lrow = tid >> 3;
    const uint32_t swz0 = (uint32_t)lrow * 128u + (((tid & 7) * 16) ^ ((lrow & 7) << 4));
    const int col0 = (tid & 7) * 8;

    // ----- ldmatrix lane addressing -----
    const int ltile = lid >> 3, lr = lid & 7;
    uint32_t a_off[2], a_xor[2];
    const uint32_t a_kadd = (ltile >> 1) * 16;
#pragma unroll
    for (int i = 0; i < 2; i++) {
        uint32_t row = wm * 32 + i * 16 + (ltile & 1) * 8 + lr;
        a_off[i] = row * 128u;
        a_xor[i] = (row & 7u) << 4;
    }
    uint32_t b_off[4], b_xor[4];
    const uint32_t b_kadd = (ltile & 1) * 16;
#pragma unroll
    for (int jb = 0; jb < 4; jb++) {
        uint32_t row = wn * 64 + jb * 16 + (ltile >> 1) * 8 + lr;
        b_off[jb] = row * 128u;
        b_xor[jb] = (row & 7u) << 4;
    }

    // ----- persistent load-side state -----
    const int niter = (cta < NTILES) ? ((NTILES - cta - 1) / grid + 1) : 0;
    const int S = niter * NK;
    int ltile_idx = cta;                          // tile being loaded
    int lc = 0;                                   // stage within load tile
    int lbuf = 0;
    const __nv_bfloat16* lpa = nullptr;
    const __nv_bfloat16* lpb = nullptr;
    if (niter > 0) {
        int bx = ltile_idx & (NBX - 1), by = ltile_idx / NBX;
        lpa = A + (size_t)(by * BM + lrow) * K + col0;
        lpb = B + (size_t)(bx * BN + lrow) * K + col0;
    }
    int li = 0;

    auto load_stage = [&]() {
        uint32_t base = sb + (uint32_t)lbuf * STAGE_BYTES + swz0;
#pragma unroll
        for (int t = 0; t < 4; t++)
            cp_async16(base + t * 4096u, lpa + (size_t)t * 32 * K);
#pragma unroll
        for (int t = 0; t < 4; t++)
            cp_async16(base + (uint32_t)A_BYTES + t * 4096u, lpb + (size_t)t * 32 * K);
        CP_COMMIT();
        li++;
        lbuf = (lbuf == NBUF - 1) ? 0 : lbuf + 1;
        lc++;
        if (lc == NK) {
            lc = 0;
            ltile_idx += grid;
            if (ltile_idx < NTILES) {
                int bx = ltile_idx & (NBX - 1), by = ltile_idx / NBX;
                lpa = A + (size_t)(by * BM + lrow) * K + col0;
                lpb = B + (size_t)(bx * BN + lrow) * K + col0;
            }
        } else {
            lpa += BKE;
            lpb += BKE;
        }
    };

    if (S >= 1) load_stage();
    if (S >= 2) load_stage();

    int ci = 0, cbuf = 0;
    const float fw = g_wfac[LAYER];
    const int g = lid >> 2, tig = lid & 3;

    for (int tile = cta; tile < NTILES; tile += grid) {
        const int bx = tile & (NBX - 1), by = tile / NBX;
        const int m0 = by * BM, n0 = bx * BN;

        float acc[2][8][4];
#pragma unroll
        for (int i = 0; i < 2; i++)
#pragma unroll
            for (int j = 0; j < 8; j++)
#pragma unroll
                for (int q = 0; q < 4; q++) acc[i][j][q] = 0.f;

        for (int c = 0; c < NK; c++) {
            int pending = li - ci;
            if (pending >= 3) { CP_WAIT(2); } else if (pending == 2) { CP_WAIT(1); } else { CP_WAIT(0); }
            __syncthreads();
            if (li < S) load_stage();

            uint32_t baseA = sb + (uint32_t)cbuf * STAGE_BYTES;
            uint32_t baseB = baseA + (uint32_t)A_BYTES;

#pragma unroll
            for (int ks = 0; ks < 4; ks++) {
                uint32_t kbA = ks * 32 + a_kadd;
                uint32_t kbB = ks * 32 + b_kadd;
                uint32_t afr[2][4];
#pragma unroll
                for (int i = 0; i < 2; i++)
                    ldmx4(afr[i][0], afr[i][1], afr[i][2], afr[i][3],
                          baseA + a_off[i] + (kbA ^ a_xor[i]));
                uint32_t bfr[8][2];
#pragma unroll
                for (int jb = 0; jb < 4; jb++) {
                    uint32_t r0, r1, r2, r3;
                    ldmx4(r0, r1, r2, r3, baseB + b_off[jb] + (kbB ^ b_xor[jb]));
                    bfr[jb * 2 + 0][0] = r0; bfr[jb * 2 + 0][1] = r1;
                    bfr[jb * 2 + 1][0] = r2; bfr[jb * 2 + 1][1] = r3;
                }
#pragma unroll
                for (int i = 0; i < 2; i++)
#pragma unroll
                    for (int j = 0; j < 8; j++)
                        mma_bf16(acc[i][j], afr[i], bfr[j]);
            }
            ci++;
            cbuf = (cbuf == NBUF - 1) ? 0 : cbuf + 1;
        }

        // ----- epilogue (next tile's loads already in flight) -----
        const int tile64 = bx * 2 + wn;
#pragma unroll
        for (int i = 0; i < 2; i++) {
            int r0 = m0 + wm * 32 + i * 16 + g;
            float fa0 = inva[r0] * fw;
            float fa1 = inva[r0 + 8] * fw;
            float ssa = 0.f, ama = 0.f, ssb = 0.f, amb = 0.f;
#pragma unroll
            for (int j = 0; j < 8; j++) {
                int n = n0 + wn * 64 + j * 8 + tig * 2;
                float bxv = bias[n], byv = bias[n + 1];
                float v0 = acc[i][j][0] * fa0 + bxv;
                float v1 = acc[i][j][1] * fa0 + byv;
                float v2 = acc[i][j][2] * fa1 + bxv;
                float v3 = acc[i][j][3] * fa1 + byv;
                if (LAYER == 0) {
                    v0 = 0.5f * v0 * (1.f + erff(v0 * 0.70710678118654752f));
                    v1 = 0.5f * v1 * (1.f + erff(v1 * 0.70710678118654752f));
                    v2 = 0.5f * v2 * (1.f + erff(v2 * 0.70710678118654752f));
                    v3 = 0.5f * v3 * (1.f + erff(v3 * 0.70710678118654752f));
                    ssa += v0 * v0 + v1 * v1;
                    ssb += v2 * v2 + v3 * v3;
                    ama = fmaxf(ama, fmaxf(fabsf(v0), fabsf(v1)));
                    amb = fmaxf(amb, fmaxf(fabsf(v2), fabsf(v3)));
                }
                *(float2*)(out + (size_t)r0 * N + n)       = make_float2(v0, v1);
                *(float2*)(out + (size_t)(r0 + 8) * N + n) = make_float2(v2, v3);
            }
            if (LAYER == 0) {
#pragma unroll
                for (int o = 1; o < 4; o <<= 1) {
                    ssa += __shfl_xor_sync(0xffffffffu, ssa, o);
                    ssb += __shfl_xor_sync(0xffffffffu, ssb, o);
                    ama = fmaxf(ama, __shfl_xor_sync(0xffffffffu, ama, o));
                    amb = fmaxf(amb, __shfl_xor_sync(0xffffffffu, amb, o));
                }
                if (tig == 0) {
                    g_hss[(size_t)r0 * 64 + tile64]       = ssa;
                    g_ham[(size_t)r0 * 64 + tile64]       = ama;
                    g_hss[(size_t)(r0 + 8) * 64 + tile64] = ssb;
                    g_ham[(size_t)(r0 + 8) * 64 + tile64] = amb;
                }
            }
        }
    }
}

// -------------------------------------------------------------------------
extern "C" void kernel_launch(void* const* d_in, const int* in_sizes, int n_in,
                              void* d_out, int out_size) {
    const float* x  = (const float*)d_in[0];
    const float* w1 = (const float*)d_in[1];
    const float* b1 = (const float*)d_in[2];
    const float* w2 = (const float*)d_in[3];
    const float* b2 = (const float*)d_in[4];
    float* out = (float*)d_out;

    const int n = INNER * DIN;

    int dev = 0, sms = 148;
    cudaGetDevice(&dev);
    cudaDeviceGetAttribute(&sms, cudaDevAttrMultiProcessorCount, dev);
    const int grid = 2 * sms;

    cudaFuncSetAttribute(gemm_bf16<0>, cudaFuncAttributeMaxDynamicSharedMemorySize, SMEM_BYTES);
    cudaFuncSetAttribute(gemm_bf16<1>, cudaFuncAttributeMaxDynamicSharedMemorySize, SMEM_BYTES);

    wabs_part<<<dim3(256, 2), 256>>>(w1, w2, n);                 // 0
    wquant<<<dim3(n / 4 / 256, 2), 256>>>(w1, w2, n);            // 1
    act_quant<<<MTOK / 8, 256>>>(x, 0);                          // 2
    gemm_bf16<0><<<grid, 256, SMEM_BYTES>>>(b1, nullptr);        // 3
    act_quant<<<MTOK / 8, 256>>>(nullptr, 1);                    // 4
    gemm_bf16<1><<<grid, 256, SMEM_BYTES>>>(b2, out);            // 5
}

// round 14
// speedup vs baseline: 1.2277x; 1.0985x over previous
#include <cuda_runtime.h>
#include <cuda_bf16.h>
#include <cstdint>

#define EPSF 1e-5f
#define QBF  127.0f

static constexpr int MTOK  = 4 * 4096;
static constexpr int DIN   = 1024;
static constexpr int INNER = 4096;

// ---------------- device scratch ----------------
__device__ float g_wfac[2];
__device__ float g_part[2][256];
__device__ __align__(16) __nv_bfloat16 g_w1q[(size_t)INNER * DIN];
__device__ __align__(16) __nv_bfloat16 g_w2q[(size_t)DIN * INNER];
__device__ __align__(16) __nv_bfloat16 g_xq [(size_t)MTOK * DIN];
__device__ float g_sx[MTOK];
__device__ __align__(16) float g_h [(size_t)MTOK * INNER];
__device__ __align__(16) __nv_bfloat16 g_hq[(size_t)MTOK * INNER];
__device__ float g_sh[MTOK];
__device__ __align__(16) float g_hss[(size_t)MTOK * 64];
__device__ __align__(16) float g_ham[(size_t)MTOK * 64];

// ---------------- helpers ----------------
__device__ __forceinline__ uint32_t smem_u32(const void* p) {
    uint32_t a;
    asm("{ .reg .u64 t; cvta.to.shared.u64 t, %1; cvt.u32.u64 %0, t; }" : "=r"(a) : "l"(p));
    return a;
}
__device__ __forceinline__ void cp_async16(uint32_t dst, const void* src) {
    asm volatile("cp.async.cg.shared.global [%0], [%1], 16;" :: "r"(dst), "l"(src) : "memory");
}
#define MBAR_INIT(a, c) asm volatile("mbarrier.init.shared.b64 [%0], %1;" :: "r"(a), "r"(c) : "memory")
#define MBAR_ARRIVE(a)  asm volatile("mbarrier.arrive.shared.b64 _, [%0];" :: "r"(a) : "memory")
// NOTE: .noinc — arrival counts against the initialized expected count.
// The default (no .noinc) increments pending count at issue and nets to zero,
// which deadlocked round 10.
#define CP_MBAR_ARRIVE(a) asm volatile("cp.async.mbarrier.arrive.noinc.shared.b64 [%0];" :: "r"(a) : "memory")
#define MBAR_WAIT(a, par) do { \
    uint32_t _m = (a), _p = (par), _d; \
    asm volatile("{\n\t.reg .pred p;\n\tmbarrier.try_wait.parity.acquire.cta.shared::cta.b64 p, [%1], %2;\n\tselp.b32 %0, 1, 0, p;\n\t}" \
        : "=r"(_d) : "r"(_m), "r"(_p) : "memory"); \
    if (!_d) { \
        asm volatile("{\n\t.reg .pred P1;\n\tWL_%=:\n\tmbarrier.try_wait.parity.acquire.cta.shared::cta.b64 P1, [%0], %1, 0x989680;\n\t@P1 bra.uni WD_%=;\n\tbra.uni WL_%=;\n\tWD_%=:\n\t}" \
            :: "r"(_m), "r"(_p) : "memory"); \
    } } while (0)

__device__ __forceinline__ void ldmx4(uint32_t& r0, uint32_t& r1, uint32_t& r2, uint32_t& r3,
                                      uint32_t addr) {
    asm volatile("ldmatrix.sync.aligned.m8n8.x4.shared.b16 {%0,%1,%2,%3}, [%4];"
                 : "=r"(r0), "=r"(r1), "=r"(r2), "=r"(r3) : "r"(addr));
}
__device__ __forceinline__ void mma_bf16(float* c, const uint32_t* a, const uint32_t* b) {
    asm volatile("mma.sync.aligned.m16n8k16.row.col.f32.bf16.bf16.f32 "
                 "{%0,%1,%2,%3}, {%4,%5,%6,%7}, {%8,%9}, {%0,%1,%2,%3};"
                 : "+f"(c[0]), "+f"(c[1]), "+f"(c[2]), "+f"(c[3])
                 : "r"(a[0]), "r"(a[1]), "r"(a[2]), "r"(a[3]), "r"(b[0]), "r"(b[1]));
}

// ---------------- weight absmean partials (both weights) -----------------
__global__ void wabs_part(const float* __restrict__ w1, const float* __restrict__ w2,
                          int n) {
    int slot = blockIdx.y;
    const float4* w4 = (const float4*)(slot ? w2 : w1);
    int nv = n >> 2;
    float s = 0.f;
    for (int i = blockIdx.x * blockDim.x + threadIdx.x; i < nv; i += gridDim.x * blockDim.x) {
        float4 v = w4[i];
        s += fabsf(v.x) + fabsf(v.y) + fabsf(v.z) + fabsf(v.w);
    }
    __shared__ float sh[256];
    sh[threadIdx.x] = s;
    __syncthreads();
    for (int o = 128; o > 0; o >>= 1) {
        if (threadIdx.x < o) sh[threadIdx.x] += sh[threadIdx.x + o];
        __syncthreads();
    }
    if (threadIdx.x == 0) g_part[slot][blockIdx.x] = sh[0];
}

// ---------------- ternary weight quant (inlines the final reduce) --------
__global__ void wquant(const float* __restrict__ w1, const float* __restrict__ w2, int n) {
    int slot = blockIdx.y;
    __shared__ float sh[256];
    sh[threadIdx.x] = g_part[slot][threadIdx.x];
    __syncthreads();
    for (int o = 128; o > 0; o >>= 1) {
        if (threadIdx.x < o) sh[threadIdx.x] += sh[threadIdx.x + o];
        __syncthreads();
    }
    float wf = fmaxf(sh[0] / (float)n, EPSF);
    if (blockIdx.x == 0 && threadIdx.x == 0) g_wfac[slot] = wf;

    const float* w = slot ? w2 : w1;
    __nv_bfloat16* q = slot ? g_w2q : g_w1q;
    int i = blockIdx.x * blockDim.x + threadIdx.x;
    int nv = n >> 2;
    if (i >= nv) return;
    float sc = 1.f / wf;
    float4 v = ((const float4*)w)[i];
    int t0 = (int)rintf(v.x * sc); t0 = t0 < -1 ? -1 : (t0 > 1 ? 1 : t0);
    int t1 = (int)rintf(v.y * sc); t1 = t1 < -1 ? -1 : (t1 > 1 ? 1 : t1);
    int t2 = (int)rintf(v.z * sc); t2 = t2 < -1 ? -1 : (t2 > 1 ? 1 : t2);
    int t3 = (int)rintf(v.w * sc); t3 = t3 < -1 ? -1 : (t3 > 1 ? 1 : t3);
    __nv_bfloat162* q2 = (__nv_bfloat162*)(q + (size_t)i * 4);
    q2[0] = __nv_bfloat162(__float2bfloat16_rn((float)t0), __float2bfloat16_rn((float)t1));
    q2[1] = __nv_bfloat162(__float2bfloat16_rn((float)t2), __float2bfloat16_rn((float)t3));
}

// ---------------- rmsnorm + absmax int8 quant, warp-per-row --------------
__global__ __launch_bounds__(256)
void act_quant(const float* __restrict__ xin, int slot) {
    const int lane = threadIdx.x & 31;
    const int wrow = blockIdx.x * 8 + (threadIdx.x >> 5);

    if (slot == 0) {
        const float4* xr = (const float4*)(xin + (size_t)wrow * DIN);
        float4 v[8];
        float ss = 0.f, am = 0.f;
#pragma unroll
        for (int i = 0; i < 8; i++) {
            float4 f = xr[lane + 32 * i];
            v[i] = f;
            ss += f.x * f.x + f.y * f.y + f.z * f.z + f.w * f.w;
            am = fmaxf(am, fmaxf(fmaxf(fabsf(f.x), fabsf(f.y)), fmaxf(fabsf(f.z), fabsf(f.w))));
        }
#pragma unroll
        for (int o = 16; o > 0; o >>= 1) {
            ss += __shfl_xor_sync(0xffffffffu, ss, o);
            am = fmaxf(am, __shfl_xor_sync(0xffffffffu, am, o));
        }
        float rn = rsqrtf(ss / (float)DIN + EPSF);
        float amn = fmaxf(am * rn, EPSF);
        float sc = QBF / amn;
        if (lane == 0) g_sx[wrow] = amn / QBF;

        uint2* qr = (uint2*)(g_xq + (size_t)wrow * DIN);
#pragma unroll
        for (int i = 0; i < 8; i++) {
            float4 f = v[i];
            int t0 = (int)rintf((f.x * rn) * sc); t0 = t0 < -128 ? -128 : (t0 > 127 ? 127 : t0);
            int t1 = (int)rintf((f.y * rn) * sc); t1 = t1 < -128 ? -128 : (t1 > 127 ? 127 : t1);
            int t2 = (int)rintf((f.z * rn) * sc); t2 = t2 < -128 ? -128 : (t2 > 127 ? 127 : t2);
            int t3 = (int)rintf((f.w * rn) * sc); t3 = t3 < -128 ? -128 : (t3 > 127 ? 127 : t3);
            __nv_bfloat162 p0(__float2bfloat16_rn((float)t0), __float2bfloat16_rn((float)t1));
            __nv_bfloat162 p1(__float2bfloat16_rn((float)t2), __float2bfloat16_rn((float)t3));
            uint2 u;
            u.x = *(uint32_t*)&p0;
            u.y = *(uint32_t*)&p1;
            qr[lane + 32 * i] = u;
        }
    } else {
        float2 s2 = ((const float2*)(g_hss + (size_t)wrow * 64))[lane];
        float2 a2 = ((const float2*)(g_ham + (size_t)wrow * 64))[lane];
        float ss = s2.x + s2.y;
        float am = fmaxf(a2.x, a2.y);
#pragma unroll
        for (int o = 16; o > 0; o >>= 1) {
            ss += __shfl_xor_sync(0xffffffffu, ss, o);
            am = fmaxf(am, __shfl_xor_sync(0xffffffffu, am, o));
        }
        float rn = rsqrtf(ss / (float)INNER + EPSF);
        float amn = fmaxf(am * rn, EPSF);
        float sc = QBF / amn;
        if (lane == 0) g_sh[wrow] = amn / QBF;

        const float4* xr = (const float4*)(g_h + (size_t)wrow * INNER);
        uint2* qr = (uint2*)(g_hq + (size_t)wrow * INNER);
#pragma unroll 4
        for (int i = 0; i < 32; i++) {
            float4 f = xr[lane + 32 * i];
            int t0 = (int)rintf((f.x * rn) * sc); t0 = t0 < -128 ? -128 : (t0 > 127 ? 127 : t0);
            int t1 = (int)rintf((f.y * rn) * sc); t1 = t1 < -128 ? -128 : (t1 > 127 ? 127 : t1);
            int t2 = (int)rintf((f.z * rn) * sc); t2 = t2 < -128 ? -128 : (t2 > 127 ? 127 : t2);
            int t3 = (int)rintf((f.w * rn) * sc); t3 = t3 < -128 ? -128 : (t3 > 127 ? 127 : t3);
            __nv_bfloat162 p0(__float2bfloat16_rn((float)t0), __float2bfloat16_rn((float)t1));
            __nv_bfloat162 p1(__float2bfloat16_rn((float)t2), __float2bfloat16_rn((float)t3));
            uint2 u;
            u.x = *(uint32_t*)&p0;
            u.y = *(uint32_t*)&p1;
            qr[lane + 32 * i] = u;
        }
    }
}

// ------- warp-specialized persistent GEMM: 8 consumer + 4 producer warps --
// CTA tile 128x128, K-stage 64 elems (32 KB), 6-slot mbarrier ring.
static constexpr int BM = 128, BN = 128, BKE = 64;
static constexpr int STAGE_BYTES = (BM + BN) * BKE * 2;     // 32 KB
static constexpr int NBUF = 6;
static constexpr int BARS_OFF = NBUF * STAGE_BYTES;          // 196608
static constexpr int SMEM_BYTES = BARS_OFF + NBUF * 16;      // + full/empty pairs

template<int LAYER>
__global__ __launch_bounds__(384, 1)
void gemm_ws(const float* __restrict__ bias, float* __restrict__ dout) {
    constexpr int K   = LAYER ? INNER : DIN;
    constexpr int N   = LAYER ? DIN : INNER;
    constexpr int NK  = K / BKE;
    constexpr int NBX = N / BN;
    constexpr int NTILES = (MTOK / BM) * NBX;

    const __nv_bfloat16* A = LAYER ? g_hq : g_xq;
    const __nv_bfloat16* B = LAYER ? g_w2q : g_w1q;
    const float* inva      = LAYER ? g_sh : g_sx;
    float* out             = LAYER ? dout : g_h;

    extern __shared__ char smem[];
    const uint32_t sb = smem_u32(smem);
    const uint32_t bar0 = sb + BARS_OFF;
    // full[i] at bar0 + 16*i, empty[i] at bar0 + 16*i + 8

    const int tid = threadIdx.x;
    const int wid = tid >> 5, lid = tid & 31;
    const int cta = blockIdx.x;
    const int grid = gridDim.x;

    if (tid == 0) {
#pragma unroll
        for (int i = 0; i < NBUF; i++) {
            MBAR_INIT(bar0 + 16 * i, 128);        // full: 128 producer threads
            MBAR_INIT(bar0 + 16 * i + 8, 256);    // empty: 256 consumer threads
        }
    }
    __syncthreads();

    const int niter = (NTILES - cta - 1) / grid + 1;
    const int S = niter * NK;

    if (wid >= 8) {
        // ================= PRODUCER (warps 8..11, 128 threads) ===========
        const int ptid = tid - 256;               // 0..127
        const int prow = ptid >> 3;                // 0..15
        const int pcol = (ptid & 7) * 8;           // elem offset
        const uint32_t dst0 = (uint32_t)prow * 128u +
                              (((uint32_t)(ptid & 7) * 16u) ^ (((uint32_t)prow & 7u) << 4));

        int ltile = cta, lc = 0;
        int bx = ltile & (NBX - 1), by = ltile / NBX;
        const __nv_bfloat16* lpa = A + (size_t)(by * BM + prow) * K + pcol;
        const __nv_bfloat16* lpb = B + (size_t)(bx * BN + prow) * K + pcol;

        int slot = 0, phase = 1;
        for (int s = 0; s < S; s++) {
            MBAR_WAIT(bar0 + 16 * slot + 8, phase);
            uint32_t dst = sb + (uint32_t)slot * STAGE_BYTES + dst0;
#pragma unroll
            for (int t = 0; t < 8; t++)                    // A: rows prow+16t
                cp_async16(dst + t * 2048u, lpa + (size_t)t * 16 * K);
#pragma unroll
            for (int t = 0; t < 8; t++)                    // B
                cp_async16(dst + 16384u + t * 2048u, lpb + (size_t)t * 16 * K);
            CP_MBAR_ARRIVE(bar0 + 16 * slot);
            slot++; if (slot == NBUF) { slot = 0; phase ^= 1; }
            lc++;
            if (lc == NK) {
                lc = 0;
                ltile += grid;
                if (ltile < NTILES) {
                    bx = ltile & (NBX - 1); by = ltile / NBX;
                    lpa = A + (size_t)(by * BM + prow) * K + pcol;
                    lpb = B + (size_t)(bx * BN + prow) * K + pcol;
                }
            } else {
                lpa += BKE;
                lpb += BKE;
            }
        }
    } else {
        // ================= CONSUMER (warps 0..7) ==========================
        const int wm = wid >> 1, wn = wid & 1;    // 4 x 2, each 32m x 64n
        const int ltile = lid >> 3, lr = lid & 7;
        uint32_t a_off[2], a_xor[2];
        const uint32_t a_kadd = (ltile >> 1) * 16;
#pragma unroll
        for (int i = 0; i < 2; i++) {
            uint32_t row = wm * 32 + i * 16 + (ltile & 1) * 8 + lr;
            a_off[i] = row * 128u;
            a_xor[i] = (row & 7u) << 4;
        }
        uint32_t b_off[4], b_xor[4];
        const uint32_t b_kadd = (ltile & 1) * 16;
#pragma unroll
        for (int jb = 0; jb < 4; jb++) {
            uint32_t row = wn * 64 + jb * 16 + (ltile >> 1) * 8 + lr;
            b_off[jb] = row * 128u;
            b_xor[jb] = (row & 7u) << 4;
        }

        const float fw = g_wfac[LAYER];
        const int g = lid >> 2, tig = lid & 3;

        int slot = 0, phase = 0;
        for (int tile = cta; tile < NTILES; tile += grid) {
            const int bx = tile & (NBX - 1), by = tile / NBX;
            const int m0 = by * BM, n0 = bx * BN;

            float acc[2][8][4];
#pragma unroll
            for (int i = 0; i < 2; i++)
#pragma unroll
                for (int j = 0; j < 8; j++)
#pragma unroll
                    for (int q = 0; q < 4; q++) acc[i][j][q] = 0.f;

            for (int c = 0; c < NK; c++) {
                MBAR_WAIT(bar0 + 16 * slot, phase);
                uint32_t baseA = sb + (uint32_t)slot * STAGE_BYTES;
                uint32_t baseB = baseA + 16384u;

#pragma unroll
                for (int ks = 0; ks < 4; ks++) {
                    uint32_t kbA = ks * 32 + a_kadd;
                    uint32_t kbB = ks * 32 + b_kadd;
                    uint32_t afr[2][4];
#pragma unroll
                    for (int i = 0; i < 2; i++)
                        ldmx4(afr[i][0], afr[i][1], afr[i][2], afr[i][3],
                              baseA + a_off[i] + (kbA ^ a_xor[i]));
                    uint32_t bfr[8][2];
#pragma unroll
                    for (int jb = 0; jb < 4; jb++) {
                        uint32_t r0, r1, r2, r3;
                        ldmx4(r0, r1, r2, r3, baseB + b_off[jb] + (kbB ^ b_xor[jb]));
                        bfr[jb * 2 + 0][0] = r0; bfr[jb * 2 + 0][1] = r1;
                        bfr[jb * 2 + 1][0] = r2; bfr[jb * 2 + 1][1] = r3;
                    }
#pragma unroll
                    for (int i = 0; i < 2; i++)
#pragma unroll
                        for (int j = 0; j < 8; j++)
                            mma_bf16(acc[i][j], afr[i], bfr[j]);
                }
                MBAR_ARRIVE(bar0 + 16 * slot + 8);
                slot++; if (slot == NBUF) { slot = 0; phase ^= 1; }
            }

            // ----- epilogue (producers keep prefetching next tile) -----
            const int tile64 = bx * 2 + wn;
#pragma unroll
            for (int i = 0; i < 2; i++) {
                int r0 = m0 + wm * 32 + i * 16 + g;
                float fa0 = inva[r0] * fw;
                float fa1 = inva[r0 + 8] * fw;
                float ssa = 0.f, ama = 0.f, ssb = 0.f, amb = 0.f;
#pragma unroll
                for (int j = 0; j < 8; j++) {
                    int n = n0 + wn * 64 + j * 8 + tig * 2;
                    float bxv = bias[n], byv = bias[n + 1];
                    float v0 = acc[i][j][0] * fa0 + bxv;
                    float v1 = acc[i][j][1] * fa0 + byv;
                    float v2 = acc[i][j][2] * fa1 + bxv;
                    float v3 = acc[i][j][3] * fa1 + byv;
                    if (LAYER == 0) {
                        v0 = 0.5f * v0 * (1.f + erff(v0 * 0.70710678118654752f));
                        v1 = 0.5f * v1 * (1.f + erff(v1 * 0.70710678118654752f));
                        v2 = 0.5f * v2 * (1.f + erff(v2 * 0.70710678118654752f));
                        v3 = 0.5f * v3 * (1.f + erff(v3 * 0.70710678118654752f));
                        ssa += v0 * v0 + v1 * v1;
                        ssb += v2 * v2 + v3 * v3;
                        ama = fmaxf(ama, fmaxf(fabsf(v0), fabsf(v1)));
                        amb = fmaxf(amb, fmaxf(fabsf(v2), fabsf(v3)));
                    }
                    *(float2*)(out + (size_t)r0 * N + n)       = make_float2(v0, v1);
                    *(float2*)(out + (size_t)(r0 + 8) * N + n) = make_float2(v2, v3);
                }
                if (LAYER == 0) {
#pragma unroll
                    for (int o = 1; o < 4; o <<= 1) {
                        ssa += __shfl_xor_sync(0xffffffffu, ssa, o);
                        ssb += __shfl_xor_sync(0xffffffffu, ssb, o);
                        ama = fmaxf(ama, __shfl_xor_sync(0xffffffffu, ama, o));
                        amb = fmaxf(amb, __shfl_xor_sync(0xffffffffu, amb, o));
                    }
                    if (tig == 0) {
                        g_hss[(size_t)r0 * 64 + tile64]       = ssa;
                        g_ham[(size_t)r0 * 64 + tile64]       = ama;
                        g_hss[(size_t)(r0 + 8) * 64 + tile64] = ssb;
                        g_ham[(size_t)(r0 + 8) * 64 + tile64] = amb;
                    }
                }
            }
        }
    }
}

// -------------------------------------------------------------------------
extern "C" void kernel_launch(void* const* d_in, const int* in_sizes, int n_in,
                              void* d_out, int out_size) {
    const float* x  = (const float*)d_in[0];
    const float* w1 = (const float*)d_in[1];
    const float* b1 = (const float*)d_in[2];
    const float* w2 = (const float*)d_in[3];
    const float* b2 = (const float*)d_in[4];
    float* out = (float*)d_out;

    const int n = INNER * DIN;

    int dev = 0, sms = 148;
    cudaGetDevice(&dev);
    cudaDeviceGetAttribute(&sms, cudaDevAttrMultiProcessorCount, dev);

    cudaFuncSetAttribute(gemm_ws<0>, cudaFuncAttributeMaxDynamicSharedMemorySize, SMEM_BYTES);
    cudaFuncSetAttribute(gemm_ws<1>, cudaFuncAttributeMaxDynamicSharedMemorySize, SMEM_BYTES);

    wabs_part<<<dim3(256, 2), 256>>>(w1, w2, n);                 // 0
    wquant<<<dim3(n / 4 / 256, 2), 256>>>(w1, w2, n);            // 1
    act_quant<<<MTOK / 8, 256>>>(x, 0);                          // 2
    gemm_ws<0><<<sms, 384, SMEM_BYTES>>>(b1, nullptr);           // 3
    act_quant<<<MTOK / 8, 256>>>(nullptr, 1);                    // 4
    gemm_ws<1><<<sms, 384, SMEM_BYTES>>>(b2, out);               // 5
}